// round 13
// baseline (speedup 1.0000x reference)
#include <cuda_runtime.h>
#include <cuda_bf16.h>
#include <cstdint>

#define NN 2048
#define BB 64
#define TT 512
#define CTAS 128
#define THREADS 256
#define PITCHB 4112                 // 2048*2 + 16 bytes, conflict-free ldmatrix rows

// ---- shared memory layout ----
#define OFF_WHI 0
#define OFF_WLO (16 * PITCHB)               // 65792
#define OFF_SPK (32 * PITCHB)               // 131584
#define SPK_STRIDE 68                       // u32 words per spike row (padded)
#define OFF_MEM (OFF_SPK + 64 * SPK_STRIDE * 4)   // 148992
#define OFF_RED (OFF_MEM + 64 * 16 * 4)           // 153088
#define OFF_LUT (OFF_RED + 8 * 64 * 16 * 4)       // 185856
#define SMEM_TOTAL (OFF_LUT + 128)                // 185984

// ---- persistent device state ----
__device__ __align__(16) __nv_bfloat16 g_Whi[NN * NN];    // [n][k] = 0.1*eff^T, hi
__device__ __align__(16) __nv_bfloat16 g_Wlo[NN * NN];    // residual
__device__ __align__(16) uint32_t g_spk0[BB * (NN / 32)]; // bit-permuted packed spikes
__device__ __align__(16) uint32_t g_spk1[BB * (NN / 32)];
__device__ uint32_t g_bar;

// Spike bit permutation: within each 16-bit half (h = k>=16), local c = k&15 sits at
//   np(c) = ((c&7)>>1)*4 + (c&1) + 2*((c>>3)&1)
// so nibble q of a half = bits {k=2q, 2q+1, 2q+8, 2q+9}: one lane's A-pair bits.

// ---- helpers ----
__device__ __forceinline__ uint32_t smem_u32(const void* p) {
    uint32_t a;
    asm("{ .reg .u64 t; cvta.to.shared.u64 t, %1; cvt.u32.u64 %0, t; }" : "=r"(a) : "l"(p));
    return a;
}

__device__ __forceinline__ void ldsm4(uint32_t* r, uint32_t addr) {
    asm volatile("ldmatrix.sync.aligned.m8n8.x4.shared.b16 {%0,%1,%2,%3}, [%4];"
                 : "=r"(r[0]), "=r"(r[1]), "=r"(r[2]), "=r"(r[3]) : "r"(addr));
}

__device__ __forceinline__ void mma_bf16(float* c, const uint32_t* a, uint32_t b0, uint32_t b1) {
    asm volatile(
        "mma.sync.aligned.m16n8k16.row.col.f32.bf16.bf16.f32 "
        "{%0,%1,%2,%3},{%4,%5,%6,%7},{%8,%9},{%0,%1,%2,%3};"
        : "+f"(c[0]), "+f"(c[1]), "+f"(c[2]), "+f"(c[3])
        : "r"(a[0]), "r"(a[1]), "r"(a[2]), "r"(a[3]), "r"(b0), "r"(b1));
}

// ---- prep: transpose + zero diag + 0.1 scale + bf16 hi/lo split, plus state init ----
__global__ void prep_kernel(const float* __restrict__ rec) {
    __shared__ float tile[32][33];
    int k = blockIdx.y * 32 + threadIdx.y;
    int n = blockIdx.x * 32 + threadIdx.x;
    tile[threadIdx.y][threadIdx.x] = rec[k * NN + n];

    int fb = blockIdx.y * gridDim.x + blockIdx.x;
    int ft = threadIdx.y * 32 + threadIdx.x;
    if (fb < 4)      g_spk0[fb * 1024 + ft] = 0u;
    else if (fb < 8) g_spk1[(fb - 4) * 1024 + ft] = 0u;
    else if (fb == 8 && ft == 0) g_bar = 0u;

    __syncthreads();
    int nn = blockIdx.x * 32 + threadIdx.y;
    int kk = blockIdx.y * 32 + threadIdx.x;
    float w = tile[threadIdx.x][threadIdx.y];      // rec[kk][nn]
    float v = (nn == kk) ? 0.0f : 0.1f * w;
    __nv_bfloat16 hi = __float2bfloat16(v);
    float resid = v - __bfloat162float(hi);
    g_Whi[nn * NN + kk] = hi;
    g_Wlo[nn * NN + kk] = __float2bfloat16(resid);
}

// ---- persistent RSNN kernel: 128 CTAs, one per 16-neuron slice, 8 warps ----
__global__ void __launch_bounds__(THREADS)
rsnn_kernel(const float* __restrict__ x, float* __restrict__ out) {
    extern __shared__ char smem[];
    const uint32_t sbase = smem_u32(smem);

    const int tid = threadIdx.x;
    const int wid = tid >> 5;           // warp = k-eighth (8 u32 spike words)
    const int lane = tid & 31;
    const int n0 = blockIdx.x * 16;

    // ---- load weight slice into SMEM once (hi + lo, pitched) ----
    for (int i = tid; i < 16 * 256; i += THREADS) {
        int row = i >> 8, c = i & 255;
        *(uint4*)(smem + OFF_WHI + row * PITCHB + c * 16) =
            *(const uint4*)(g_Whi + (size_t)(n0 + row) * NN + c * 8);
        *(uint4*)(smem + OFF_WLO + row * PITCHB + c * 16) =
            *(const uint4*)(g_Wlo + (size_t)(n0 + row) * NN + c * 8);
    }
    for (int i = tid; i < 64 * 16; i += THREADS)
        ((float*)(smem + OFF_MEM))[i] = 0.0f;
    // nibble -> (a_low, a_high) bf16x2 LUT; conflict-free bank sweep
    if (tid < 16) {
        uint2 e;
        e.x = ((tid & 1) ? 0x00003F80u : 0u) | ((tid & 2) ? 0x3F800000u : 0u);
        e.y = ((tid & 4) ? 0x00003F80u : 0u) | ((tid & 8) ? 0x3F800000u : 0u);
        ((uint2*)(smem + OFF_LUT))[tid] = e;
    }
    __syncthreads();

    // per-thread constants (GEMM)
    const int rowq = lane >> 2;           // 0..7
    const int q4 = (lane & 3) * 4;        // nibble shift within a 16-bit half
    const int lc = lane & 3;
    uint32_t ldsm_off;
    {
        int grp = lane >> 3;                          // 8x8 matrix select
        int row = ((grp >> 1) << 3) + (lane & 7);     // local neuron row 0..15
        int koff = (grp & 1) * 8;
        ldsm_off = row * PITCHB + koff * 2;
    }

    // ---- hoist ALL B fragments (hi + lo) into registers: loaded ONCE ----
    uint32_t bhr[8][2][4], blr[8][2][4];
    #pragma unroll
    for (int j = 0; j < 8; ++j) {
        const int widx = (wid << 3) + j;
        #pragma unroll
        for (int h = 0; h < 2; ++h) {
            const int kt = widx * 2 + h;
            ldsm4(bhr[j][h], sbase + OFF_WHI + ldsm_off + kt * 32);
            ldsm4(blr[j][h], sbase + OFF_WLO + ldsm_off + kt * 32);
        }
    }

    // per-thread constants (epilogue: 256 threads, 4 cols each)
    const int eb = tid >> 2;              // batch row 0..63
    const int eq = (tid & 3) * 4;         // col base 0..12
    const int wsel = n0 >> 5;
    const int hsh = ((n0 >> 4) & 1) * 16;

    int npos[4];
    uint32_t pmask[4];
    #pragma unroll
    for (int i = 0; i < 4; ++i) {
        int c = eq + i;
        npos[i] = ((c & 7) >> 1) * 4 + (c & 1) + 2 * ((c >> 3) & 1);
        pmask[i] = 1u << (hsh + npos[i]);
    }
    // swizzled reduce pair offsets (pair swizzle: p = (cp + ((eb&2)<<1)) & 7)
    const int cp0 = (tid & 3) * 2;
    const int rp0 = eb * 16 + ((cp0 + ((eb & 2) << 1)) & 7) * 2;
    const int rp1 = eb * 16 + (((cp0 + 1) + ((eb & 2) << 1)) & 7) * 2;

    uint32_t* const spkS = (uint32_t*)(smem + OFF_SPK);
    float* const memS = (float*)(smem + OFF_MEM);
    float* const redS = (float*)(smem + OFF_RED);
    const uint2* const lutS = (const uint2*)(smem + OFF_LUT);

    for (int t = 0; t < TT; ++t) {
        const uint32_t* gsrc = (t & 1) ? g_spk1 : g_spk0;
        uint32_t* gdst = (t & 1) ? g_spk0 : g_spk1;

        // ---- prefetch x for this step ----
        float4 xv = __ldg((const float4*)(x + ((size_t)eb * TT + t) * NN + n0 + eq));

        // ---- per-warp staging: warp w loads ONLY its own 8 spike words ----
        // (GEMM below reads exclusively words 8w..8w+7 -> __syncwarp suffices)
        {
            const uint4* src4 = (const uint4*)gsrc;
            #pragma unroll
            for (int ii = 0; ii < 4; ++ii) {
                int item = lane + ii * 32;        // 0..127
                int row = item >> 1, half = item & 1;
                uint4 v = __ldcg(src4 + row * 16 + wid * 2 + half);
                *(uint4*)(smem + OFF_SPK + (row * SPK_STRIDE + wid * 8 + half * 4) * 4) = v;
            }
            __syncwarp();
        }

        // ---- GEMM: warp owns a k-eighth, B resident in registers ----
        float acc[4][2][4];
        #pragma unroll
        for (int m = 0; m < 4; ++m)
            #pragma unroll
            for (int nh = 0; nh < 2; ++nh)
                #pragma unroll
                for (int e = 0; e < 4; ++e) acc[m][nh][e] = 0.0f;

        #pragma unroll
        for (int j = 0; j < 8; ++j) {
            const int widx = (wid << 3) + j;          // u32 spike word index
            #pragma unroll
            for (int m = 0; m < 4; ++m) {
                const uint32_t w0 = spkS[(m * 16 + rowq) * SPK_STRIDE + widx];
                const uint32_t w1 = spkS[(m * 16 + rowq + 8) * SPK_STRIDE + widx];
                #pragma unroll
                for (int h = 0; h < 2; ++h) {
                    uint2 u0 = lutS[(w0 >> (h * 16 + q4)) & 0xFu];
                    uint2 u1 = lutS[(w1 >> (h * 16 + q4)) & 0xFu];
                    uint32_t a[4] = {u0.x, u1.x, u0.y, u1.y};
                    mma_bf16(acc[m][0], a, bhr[j][h][0], bhr[j][h][1]);
                    mma_bf16(acc[m][1], a, bhr[j][h][2], bhr[j][h][3]);
                    mma_bf16(acc[m][0], a, blr[j][h][0], blr[j][h][1]);
                    mma_bf16(acc[m][1], a, blr[j][h][2], blr[j][h][3]);
                }
            }
        }

        // ---- dump per-warp partials (pair-swizzled: conflict-free) ----
        {
            float* pwrt = redS + wid * 1024;
            #pragma unroll
            for (int m = 0; m < 4; ++m)
                #pragma unroll
                for (int nh = 0; nh < 2; ++nh) {
                    const int mycp = nh * 4 + lc;
                    const int r0 = m * 16 + rowq;
                    const int sw = ((mycp + ((r0 & 2) << 1)) & 7) * 2;
                    *(float2*)(pwrt + r0 * 16 + sw) = make_float2(acc[m][nh][0], acc[m][nh][1]);
                    *(float2*)(pwrt + (r0 + 8) * 16 + sw) = make_float2(acc[m][nh][2], acc[m][nh][3]);
                }
        }
        __syncthreads();   // the ONE block sync: orders all slices + all dumps

        // prev-spike word (may live in another warp's staged slice -> after sync)
        const uint32_t pw = spkS[eb * SPK_STRIDE + wsel];

        // ---- reduce 8 partials + LIF epilogue (4 cols per thread) ----
        float2 sa = *(float2*)(redS + rp0);
        float2 sb = *(float2*)(redS + rp1);
        #pragma unroll
        for (int w = 1; w < 8; ++w) {
            float2 pa = *(float2*)(redS + w * 1024 + rp0);
            float2 pb = *(float2*)(redS + w * 1024 + rp1);
            sa.x += pa.x; sa.y += pa.y;
            sb.x += pb.x; sb.y += pb.y;
        }

        float4 mv = *(float4*)(memS + eb * 16 + eq);
        float cur0 = xv.x + sa.x, cur1 = xv.y + sa.y;
        float cur2 = xv.z + sb.x, cur3 = xv.w + sb.y;
        float m0 = (pw & pmask[0]) ? cur0 : fmaf(0.96f, mv.x, cur0);
        float m1 = (pw & pmask[1]) ? cur1 : fmaf(0.96f, mv.y, cur1);
        float m2 = (pw & pmask[2]) ? cur2 : fmaf(0.96f, mv.z, cur2);
        float m3 = (pw & pmask[3]) ? cur3 : fmaf(0.96f, mv.w, cur3);

        unsigned s0 = (m0 >= 0.5f), s1 = (m1 >= 0.5f);
        unsigned s2 = (m2 >= 0.5f), s3 = (m3 >= 0.5f);

        *(float4*)(memS + eb * 16 + eq) = make_float4(m0, m1, m2, m3);

        // pack new spike bits (permuted positions) -> u16 per (batch row, CTA)
        unsigned v = (s0 << npos[0]) | (s1 << npos[1]) | (s2 << npos[2]) | (s3 << npos[3]);
        v |= __shfl_xor_sync(0xFFFFFFFFu, v, 1);
        v |= __shfl_xor_sync(0xFFFFFFFFu, v, 2);
        if ((tid & 3) == 0)
            ((uint16_t*)gdst)[eb * 128 + blockIdx.x] = (uint16_t)v;

        // ---- arrive after all publishes, then PER-WARP poll ----
        __syncthreads();
        if (tid == 0)
            asm volatile("red.release.gpu.global.add.u32 [%0], 1;" :: "l"(&g_bar) : "memory");

        *(float4*)(out + ((size_t)eb * TT + t) * NN + n0 + eq) =
            make_float4((float)s0, (float)s1, (float)s2, (float)s3);

        {
            const unsigned tgt = (unsigned)(CTAS * (t + 1));
            if (lane == 0) {
                unsigned bv;
                do {
                    asm volatile("ld.acquire.gpu.global.u32 %0, [%1];"
                                 : "=r"(bv) : "l"(&g_bar) : "memory");
                } while (bv < tgt);
            }
            __syncwarp();
        }
        // warps proceed independently into next step's per-warp staging
    }
}

// ---- launch ----
extern "C" void kernel_launch(void* const* d_in, const int* in_sizes, int n_in,
                              void* d_out, int out_size) {
    const float* x = (const float*)d_in[0];
    const float* rec = (const float*)d_in[1];
    if (n_in >= 2 && in_sizes[0] == NN * NN) {
        x = (const float*)d_in[1];
        rec = (const float*)d_in[0];
    }
    float* out = (float*)d_out;

    cudaFuncSetAttribute(rsnn_kernel, cudaFuncAttributeMaxDynamicSharedMemorySize, SMEM_TOTAL);

    dim3 cg(NN / 32, NN / 32), cb(32, 32);
    prep_kernel<<<cg, cb>>>(rec);
    rsnn_kernel<<<CTAS, THREADS, SMEM_TOTAL>>>(x, out);
}

// round 14
// speedup vs baseline: 1.1329x; 1.1329x over previous
#include <cuda_runtime.h>
#include <cuda_bf16.h>
#include <cstdint>

#define NN 2048
#define BB 64
#define TT 512
#define CTAS 128
#define THREADS 256
#define PITCHB 4112                 // 2048*2 + 16 bytes, conflict-free ldmatrix rows

// ---- shared memory layout ----
#define OFF_WHI 0
#define OFF_WLO (16 * PITCHB)               // 65792
#define OFF_SPK (32 * PITCHB)               // 131584
#define SPK_STRIDE 68                       // u32 words per spike row (padded)
#define OFF_MEM (OFF_SPK + 64 * SPK_STRIDE * 4)   // 148992
#define OFF_RED (OFF_MEM + 64 * 16 * 4)           // 153088
#define OFF_LUT (OFF_RED + 8 * 64 * 16 * 4)       // 185856
#define SMEM_TOTAL (OFF_LUT + 128)                // 185984

// ---- persistent device state ----
__device__ __align__(16) __nv_bfloat16 g_Whi[NN * NN];    // [n][k] = 0.1*eff^T, hi
__device__ __align__(16) __nv_bfloat16 g_Wlo[NN * NN];    // residual
__device__ __align__(16) uint32_t g_spk0[BB * (NN / 32)]; // bit-permuted packed spikes
__device__ __align__(16) uint32_t g_spk1[BB * (NN / 32)];
__device__ uint32_t g_bar;     // arrival counter (hot, written by REDG/atom)
__device__ uint32_t g_flag;    // step-release flag (read-only for pollers)

// Spike bit permutation: within each 16-bit half (h = k>=16), local c = k&15 sits at
//   np(c) = ((c&7)>>1)*4 + (c&1) + 2*((c>>3)&1)
// so nibble q of a half = bits {k=2q, 2q+1, 2q+8, 2q+9}: one lane's A-pair bits.

// ---- helpers ----
__device__ __forceinline__ uint32_t smem_u32(const void* p) {
    uint32_t a;
    asm("{ .reg .u64 t; cvta.to.shared.u64 t, %1; cvt.u32.u64 %0, t; }" : "=r"(a) : "l"(p));
    return a;
}

__device__ __forceinline__ void ldsm4(uint32_t* r, uint32_t addr) {
    asm volatile("ldmatrix.sync.aligned.m8n8.x4.shared.b16 {%0,%1,%2,%3}, [%4];"
                 : "=r"(r[0]), "=r"(r[1]), "=r"(r[2]), "=r"(r[3]) : "r"(addr));
}

__device__ __forceinline__ void mma_bf16(float* c, const uint32_t* a, uint32_t b0, uint32_t b1) {
    asm volatile(
        "mma.sync.aligned.m16n8k16.row.col.f32.bf16.bf16.f32 "
        "{%0,%1,%2,%3},{%4,%5,%6,%7},{%8,%9},{%0,%1,%2,%3};"
        : "+f"(c[0]), "+f"(c[1]), "+f"(c[2]), "+f"(c[3])
        : "r"(a[0]), "r"(a[1]), "r"(a[2]), "r"(a[3]), "r"(b0), "r"(b1));
}

// ---- prep: transpose + zero diag + 0.1 scale + bf16 hi/lo split, plus state init ----
__global__ void prep_kernel(const float* __restrict__ rec) {
    __shared__ float tile[32][33];
    int k = blockIdx.y * 32 + threadIdx.y;
    int n = blockIdx.x * 32 + threadIdx.x;
    tile[threadIdx.y][threadIdx.x] = rec[k * NN + n];

    int fb = blockIdx.y * gridDim.x + blockIdx.x;
    int ft = threadIdx.y * 32 + threadIdx.x;
    if (fb < 4)      g_spk0[fb * 1024 + ft] = 0u;
    else if (fb < 8) g_spk1[(fb - 4) * 1024 + ft] = 0u;
    else if (fb == 8 && ft == 0) { g_bar = 0u; g_flag = 0u; }

    __syncthreads();
    int nn = blockIdx.x * 32 + threadIdx.y;
    int kk = blockIdx.y * 32 + threadIdx.x;
    float w = tile[threadIdx.x][threadIdx.y];      // rec[kk][nn]
    float v = (nn == kk) ? 0.0f : 0.1f * w;
    __nv_bfloat16 hi = __float2bfloat16(v);
    float resid = v - __bfloat162float(hi);
    g_Whi[nn * NN + kk] = hi;
    g_Wlo[nn * NN + kk] = __float2bfloat16(resid);
}

// ---- persistent RSNN kernel: 128 CTAs, one per 16-neuron slice, 8 warps ----
__global__ void __launch_bounds__(THREADS, 1)
rsnn_kernel(const float* __restrict__ x, float* __restrict__ out) {
    extern __shared__ char smem[];
    const uint32_t sbase = smem_u32(smem);

    const int tid = threadIdx.x;
    const int wid = tid >> 5;           // warp = k-eighth
    const int lane = tid & 31;
    const int n0 = blockIdx.x * 16;

    // ---- load weight slice into SMEM once (hi + lo, pitched) ----
    for (int i = tid; i < 16 * 256; i += THREADS) {
        int row = i >> 8, c = i & 255;
        *(uint4*)(smem + OFF_WHI + row * PITCHB + c * 16) =
            *(const uint4*)(g_Whi + (size_t)(n0 + row) * NN + c * 8);
        *(uint4*)(smem + OFF_WLO + row * PITCHB + c * 16) =
            *(const uint4*)(g_Wlo + (size_t)(n0 + row) * NN + c * 8);
    }
    for (int i = tid; i < 64 * 16; i += THREADS)
        ((float*)(smem + OFF_MEM))[i] = 0.0f;
    // nibble -> (a_low, a_high) bf16x2 LUT; conflict-free bank sweep
    if (tid < 16) {
        uint2 e;
        e.x = ((tid & 1) ? 0x00003F80u : 0u) | ((tid & 2) ? 0x3F800000u : 0u);
        e.y = ((tid & 4) ? 0x00003F80u : 0u) | ((tid & 8) ? 0x3F800000u : 0u);
        ((uint2*)(smem + OFF_LUT))[tid] = e;
    }
    __syncthreads();

    // per-thread constants (GEMM)
    const int rowq = lane >> 2;           // 0..7
    const int q4 = (lane & 3) * 4;        // nibble shift within a 16-bit half
    const int lc = lane & 3;
    uint32_t ldsm_off;
    {
        int grp = lane >> 3;
        int row = ((grp >> 1) << 3) + (lane & 7);
        int koff = (grp & 1) * 8;
        ldsm_off = row * PITCHB + koff * 2;
    }
    // per-thread constants (epilogue: 256 threads, 4 cols each)
    const int eb = tid >> 2;              // batch row 0..63
    const int eq = (tid & 3) * 4;         // col base 0..12
    const int wsel = n0 >> 5;
    const int hsh = ((n0 >> 4) & 1) * 16;

    int npos[4];
    uint32_t pmask[4];
    #pragma unroll
    for (int i = 0; i < 4; ++i) {
        int c = eq + i;
        npos[i] = ((c & 7) >> 1) * 4 + (c & 1) + 2 * ((c >> 3) & 1);
        pmask[i] = 1u << (hsh + npos[i]);
    }
    // pair-swizzled reduce offsets (conflict-free: phys = (cp + ((eb&2)<<1)) & 7)
    const int cp0 = (tid & 3) * 2;
    const int rp0 = eb * 16 + ((cp0 + ((eb & 2) << 1)) & 7) * 2;
    const int rp1 = eb * 16 + (((cp0 + 1) + ((eb & 2) << 1)) & 7) * 2;

    uint32_t* const spkS = (uint32_t*)(smem + OFF_SPK);
    float* const memS = (float*)(smem + OFF_MEM);
    float* const redS = (float*)(smem + OFF_RED);
    const uint2* const lutS = (const uint2*)(smem + OFF_LUT);

    for (int t = 0; t < TT; ++t) {
        const uint32_t* gsrc = (t & 1) ? g_spk1 : g_spk0;
        uint32_t* gdst = (t & 1) ? g_spk0 : g_spk1;

        // ---- prefetch x for this step ----
        float4 xv = __ldg((const float4*)(x + ((size_t)eb * TT + t) * NN + n0 + eq));

        // ---- stage packed spikes [64 x 64 u32] -> padded SMEM rows ----
        {
            const uint4* src = (const uint4*)gsrc;
            #pragma unroll
            for (int i = tid; i < 1024; i += THREADS) {
                int row = i >> 4, c4 = i & 15;
                uint4 v = __ldcg(src + i);
                *(uint4*)(smem + OFF_SPK + (row * SPK_STRIDE + c4 * 4) * 4) = v;
            }
        }
        __syncthreads();

        // ---- GEMM: warp owns a k-eighth, all 4 m-tiles; A via nibble LUT ----
        float acc[4][2][4];
        #pragma unroll
        for (int m = 0; m < 4; ++m)
            #pragma unroll
            for (int nh = 0; nh < 2; ++nh)
                #pragma unroll
                for (int e = 0; e < 4; ++e) acc[m][nh][e] = 0.0f;

        #pragma unroll 2
        for (int j = 0; j < 8; ++j) {
            const int widx = (wid << 3) + j;          // u32 spike word index
            uint32_t bh[2][4], bl[2][4];
            #pragma unroll
            for (int h = 0; h < 2; ++h) {
                const int kt = widx * 2 + h;
                ldsm4(bh[h], sbase + OFF_WHI + ldsm_off + kt * 32);
                ldsm4(bl[h], sbase + OFF_WLO + ldsm_off + kt * 32);
            }
            #pragma unroll
            for (int m = 0; m < 4; ++m) {
                const uint32_t w0 = spkS[(m * 16 + rowq) * SPK_STRIDE + widx];
                const uint32_t w1 = spkS[(m * 16 + rowq + 8) * SPK_STRIDE + widx];
                #pragma unroll
                for (int h = 0; h < 2; ++h) {
                    uint2 u0 = lutS[(w0 >> (h * 16 + q4)) & 0xFu];
                    uint2 u1 = lutS[(w1 >> (h * 16 + q4)) & 0xFu];
                    uint32_t a[4] = {u0.x, u1.x, u0.y, u1.y};
                    mma_bf16(acc[m][0], a, bh[h][0], bh[h][1]);
                    mma_bf16(acc[m][1], a, bh[h][2], bh[h][3]);
                    mma_bf16(acc[m][0], a, bl[h][0], bl[h][1]);
                    mma_bf16(acc[m][1], a, bl[h][2], bl[h][3]);
                }
            }
        }

        // ---- dump per-warp partials (pair-swizzled: conflict-free STS.64) ----
        {
            float* pwrt = redS + wid * 1024;
            #pragma unroll
            for (int m = 0; m < 4; ++m)
                #pragma unroll
                for (int nh = 0; nh < 2; ++nh) {
                    const int mycp = nh * 4 + lc;
                    const int r0 = m * 16 + rowq;
                    const int sw = ((mycp + ((r0 & 2) << 1)) & 7) * 2;
                    *(float2*)(pwrt + r0 * 16 + sw) = make_float2(acc[m][nh][0], acc[m][nh][1]);
                    *(float2*)(pwrt + (r0 + 8) * 16 + sw) = make_float2(acc[m][nh][2], acc[m][nh][3]);
                }
        }
        __syncthreads();

        // ---- reduce 8 partials + LIF epilogue (4 cols per thread) ----
        float2 sa = *(float2*)(redS + rp0);
        float2 sb = *(float2*)(redS + rp1);
        #pragma unroll
        for (int w = 1; w < 8; ++w) {
            float2 pa = *(float2*)(redS + w * 1024 + rp0);
            float2 pb = *(float2*)(redS + w * 1024 + rp1);
            sa.x += pa.x; sa.y += pa.y;
            sb.x += pb.x; sb.y += pb.y;
        }

        float4 mv = *(float4*)(memS + eb * 16 + eq);
        const uint32_t pw = spkS[eb * SPK_STRIDE + wsel];

        float cur0 = xv.x + sa.x, cur1 = xv.y + sa.y;
        float cur2 = xv.z + sb.x, cur3 = xv.w + sb.y;
        float m0 = (pw & pmask[0]) ? cur0 : fmaf(0.96f, mv.x, cur0);
        float m1 = (pw & pmask[1]) ? cur1 : fmaf(0.96f, mv.y, cur1);
        float m2 = (pw & pmask[2]) ? cur2 : fmaf(0.96f, mv.z, cur2);
        float m3 = (pw & pmask[3]) ? cur3 : fmaf(0.96f, mv.w, cur3);

        unsigned s0 = (m0 >= 0.5f), s1 = (m1 >= 0.5f);
        unsigned s2 = (m2 >= 0.5f), s3 = (m3 >= 0.5f);

        *(float4*)(memS + eb * 16 + eq) = make_float4(m0, m1, m2, m3);

        // pack new spike bits (permuted positions) -> u16 per (batch row, CTA)
        unsigned v = (s0 << npos[0]) | (s1 << npos[1]) | (s2 << npos[2]) | (s3 << npos[3]);
        v |= __shfl_xor_sync(0xFFFFFFFFu, v, 1);
        v |= __shfl_xor_sync(0xFFFFFFFFu, v, 2);
        if ((tid & 3) == 0)
            ((uint16_t*)gdst)[eb * 128 + blockIdx.x] = (uint16_t)v;

        // ---- publish rendezvous, then FLAG-BROADCAST barrier ----
        __syncthreads();
        if (tid == 0) {
            unsigned old;
            asm volatile("atom.release.gpu.global.add.u32 %0, [%1], 1;"
                         : "=r"(old) : "l"(&g_bar) : "memory");
            if (old == (unsigned)(CTAS * (t + 1)) - 1u)
                asm volatile("st.release.gpu.global.u32 [%0], %1;"
                             :: "l"(&g_flag), "r"((unsigned)(t + 1)) : "memory");
        }

        // out-store overlaps the flag wait
        *(float4*)(out + ((size_t)eb * TT + t) * NN + n0 + eq) =
            make_float4((float)s0, (float)s1, (float)s2, (float)s3);

        // per-warp poll of the read-only flag (no atomic contention)
        {
            if (lane == 0) {
                unsigned fv;
                do {
                    asm volatile("ld.acquire.gpu.global.u32 %0, [%1];"
                                 : "=r"(fv) : "l"(&g_flag) : "memory");
                } while (fv < (unsigned)(t + 1));
            }
            __syncwarp();
        }
        // warps proceed; next stage __syncthreads restores block order
    }
}

// ---- launch ----
extern "C" void kernel_launch(void* const* d_in, const int* in_sizes, int n_in,
                              void* d_out, int out_size) {
    const float* x = (const float*)d_in[0];
    const float* rec = (const float*)d_in[1];
    if (n_in >= 2 && in_sizes[0] == NN * NN) {
        x = (const float*)d_in[1];
        rec = (const float*)d_in[0];
    }
    float* out = (float*)d_out;

    cudaFuncSetAttribute(rsnn_kernel, cudaFuncAttributeMaxDynamicSharedMemorySize, SMEM_TOTAL);

    dim3 cg(NN / 32, NN / 32), cb(32, 32);
    prep_kernel<<<cg, cb>>>(rec);
    rsnn_kernel<<<CTAS, THREADS, SMEM_TOTAL>>>(x, out);
}

// round 15
// speedup vs baseline: 1.3223x; 1.1672x over previous
#include <cuda_runtime.h>
#include <cuda_bf16.h>
#include <cstdint>

#define NN 2048
#define BB 64
#define TT 512
#define CTAS 128
#define THREADS 256
#define PITCHB 4112                 // 2048*2 + 16 bytes, conflict-free ldmatrix rows

// ---- shared memory layout ----
#define OFF_WHI 0
#define OFF_WLO (16 * PITCHB)               // 65792
#define OFF_SPK (32 * PITCHB)               // 131584
#define SPK_STRIDE 68                       // u32 words per spike row (padded)
#define OFF_MEM (OFF_SPK + 64 * SPK_STRIDE * 4)   // 148992
#define OFF_RED (OFF_MEM + 64 * 16 * 4)           // 153088
#define OFF_LUT (OFF_RED + 8 * 64 * 16 * 4)       // 185856
#define SMEM_TOTAL (OFF_LUT + 128)                // 185984

// ---- persistent device state ----
__device__ __align__(16) __nv_bfloat16 g_Whi[NN * NN];    // [n][k] = 0.1*eff^T, hi
__device__ __align__(16) __nv_bfloat16 g_Wlo[NN * NN];    // residual
__device__ __align__(16) uint32_t g_spk0[BB * (NN / 32)]; // bit-permuted packed spikes
__device__ __align__(16) uint32_t g_spk1[BB * (NN / 32)];
__device__ uint32_t g_bar;

// Spike bit permutation: within each 16-bit half (h = k>=16), local c = k&15 sits at
//   np(c) = ((c&7)>>1)*4 + (c&1) + 2*((c>>3)&1)
// so nibble q of a half = bits {k=2q, 2q+1, 2q+8, 2q+9}: one lane's A-pair bits.

// ---- helpers ----
__device__ __forceinline__ uint32_t smem_u32(const void* p) {
    uint32_t a;
    asm("{ .reg .u64 t; cvta.to.shared.u64 t, %1; cvt.u32.u64 %0, t; }" : "=r"(a) : "l"(p));
    return a;
}

__device__ __forceinline__ void ldsm4(uint32_t* r, uint32_t addr) {
    asm volatile("ldmatrix.sync.aligned.m8n8.x4.shared.b16 {%0,%1,%2,%3}, [%4];"
                 : "=r"(r[0]), "=r"(r[1]), "=r"(r[2]), "=r"(r[3]) : "r"(addr));
}

__device__ __forceinline__ void mma_bf16(float* c, const uint32_t* a, uint32_t b0, uint32_t b1) {
    asm volatile(
        "mma.sync.aligned.m16n8k16.row.col.f32.bf16.bf16.f32 "
        "{%0,%1,%2,%3},{%4,%5,%6,%7},{%8,%9},{%0,%1,%2,%3};"
        : "+f"(c[0]), "+f"(c[1]), "+f"(c[2]), "+f"(c[3])
        : "r"(a[0]), "r"(a[1]), "r"(a[2]), "r"(a[3]), "r"(b0), "r"(b1));
}

// ---- prep: transpose + zero diag + 0.1 scale + bf16 hi/lo split, plus state init ----
__global__ void prep_kernel(const float* __restrict__ rec) {
    __shared__ float tile[32][33];
    int k = blockIdx.y * 32 + threadIdx.y;
    int n = blockIdx.x * 32 + threadIdx.x;
    tile[threadIdx.y][threadIdx.x] = rec[k * NN + n];

    int fb = blockIdx.y * gridDim.x + blockIdx.x;
    int ft = threadIdx.y * 32 + threadIdx.x;
    if (fb < 4)      g_spk0[fb * 1024 + ft] = 0u;
    else if (fb < 8) g_spk1[(fb - 4) * 1024 + ft] = 0u;
    else if (fb == 8 && ft == 0) g_bar = 0u;

    __syncthreads();
    int nn = blockIdx.x * 32 + threadIdx.y;
    int kk = blockIdx.y * 32 + threadIdx.x;
    float w = tile[threadIdx.x][threadIdx.y];      // rec[kk][nn]
    float v = (nn == kk) ? 0.0f : 0.1f * w;
    __nv_bfloat16 hi = __float2bfloat16(v);
    float resid = v - __bfloat162float(hi);
    g_Whi[nn * NN + kk] = hi;
    g_Wlo[nn * NN + kk] = __float2bfloat16(resid);
}

// ---- persistent RSNN kernel: 128 CTAs, one per 16-neuron slice, 8 warps ----
__global__ void __launch_bounds__(THREADS)
rsnn_kernel(const float* __restrict__ x, float* __restrict__ out) {
    extern __shared__ char smem[];
    const uint32_t sbase = smem_u32(smem);

    const int tid = threadIdx.x;
    const int wid = tid >> 5;           // warp = k-eighth (8 u32 spike words)
    const int lane = tid & 31;
    const int n0 = blockIdx.x * 16;

    // ---- load weight slice into SMEM once (hi + lo, pitched) ----
    for (int i = tid; i < 16 * 256; i += THREADS) {
        int row = i >> 8, c = i & 255;
        *(uint4*)(smem + OFF_WHI + row * PITCHB + c * 16) =
            *(const uint4*)(g_Whi + (size_t)(n0 + row) * NN + c * 8);
        *(uint4*)(smem + OFF_WLO + row * PITCHB + c * 16) =
            *(const uint4*)(g_Wlo + (size_t)(n0 + row) * NN + c * 8);
    }
    for (int i = tid; i < 64 * 16; i += THREADS)
        ((float*)(smem + OFF_MEM))[i] = 0.0f;
    // nibble -> (a_low, a_high) bf16x2 LUT; conflict-free bank sweep
    if (tid < 16) {
        uint2 e;
        e.x = ((tid & 1) ? 0x00003F80u : 0u) | ((tid & 2) ? 0x3F800000u : 0u);
        e.y = ((tid & 4) ? 0x00003F80u : 0u) | ((tid & 8) ? 0x3F800000u : 0u);
        ((uint2*)(smem + OFF_LUT))[tid] = e;
    }
    __syncthreads();

    // per-thread constants (GEMM)
    const int rowq = lane >> 2;           // 0..7
    const int q4 = (lane & 3) * 4;        // nibble shift within a 16-bit half
    const int lc = lane & 3;
    uint32_t ldsm_off;
    {
        int grp = lane >> 3;                          // 8x8 matrix select
        int row = ((grp >> 1) << 3) + (lane & 7);     // local neuron row 0..15
        int koff = (grp & 1) * 8;
        ldsm_off = row * PITCHB + koff * 2;
    }

    // ---- hoist ALL B fragments (hi + lo) into registers: loaded ONCE ----
    uint32_t bhr[8][2][4], blr[8][2][4];
    #pragma unroll
    for (int j = 0; j < 8; ++j) {
        const int widx = (wid << 3) + j;
        #pragma unroll
        for (int h = 0; h < 2; ++h) {
            const int kt = widx * 2 + h;
            ldsm4(bhr[j][h], sbase + OFF_WHI + ldsm_off + kt * 32);
            ldsm4(blr[j][h], sbase + OFF_WLO + ldsm_off + kt * 32);
        }
    }

    // per-thread constants (epilogue: 256 threads, 4 cols each)
    const int eb = tid >> 2;              // batch row 0..63
    const int eq = (tid & 3) * 4;         // col base 0..12
    const int wsel = n0 >> 5;
    const int hsh = ((n0 >> 4) & 1) * 16;

    int npos[4];
    uint32_t pmask[4];
    #pragma unroll
    for (int i = 0; i < 4; ++i) {
        int c = eq + i;
        npos[i] = ((c & 7) >> 1) * 4 + (c & 1) + 2 * ((c >> 3) & 1);
        pmask[i] = 1u << (hsh + npos[i]);
    }
    // swizzled reduce pair offsets (pair swizzle: p = (cp + ((eb&2)<<1)) & 7)
    const int cp0 = (tid & 3) * 2;
    const int rp0 = eb * 16 + ((cp0 + ((eb & 2) << 1)) & 7) * 2;
    const int rp1 = eb * 16 + (((cp0 + 1) + ((eb & 2) << 1)) & 7) * 2;

    uint32_t* const spkS = (uint32_t*)(smem + OFF_SPK);
    float* const memS = (float*)(smem + OFF_MEM);
    float* const redS = (float*)(smem + OFF_RED);
    const uint2* const lutS = (const uint2*)(smem + OFF_LUT);

    for (int t = 0; t < TT; ++t) {
        const uint32_t* gsrc = (t & 1) ? g_spk1 : g_spk0;
        uint32_t* gdst = (t & 1) ? g_spk0 : g_spk1;

        // ---- prefetch x for this step ----
        float4 xv = __ldg((const float4*)(x + ((size_t)eb * TT + t) * NN + n0 + eq));

        // ---- stage packed spikes [64 x 64 u32] -> padded SMEM rows ----
        {
            const uint4* src = (const uint4*)gsrc;
            #pragma unroll
            for (int i = tid; i < 1024; i += THREADS) {
                int row = i >> 4, c4 = i & 15;
                uint4 v = __ldcg(src + i);
                *(uint4*)(smem + OFF_SPK + (row * SPK_STRIDE + c4 * 4) * 4) = v;
            }
        }
        __syncthreads();

        // prev-spike word (reset mask) — hoisted off the post-dump critical path
        const uint32_t pw = spkS[eb * SPK_STRIDE + wsel];

        // ---- GEMM: warp owns a k-eighth, B resident in registers ----
        // m-outer / j-inner with vectorized uint4 spike-word loads:
        // 16 LDS.128 per thread instead of 64 LDS.32 (conflict-free phases).
        float acc[4][2][4];
        #pragma unroll
        for (int m = 0; m < 4; ++m)
            #pragma unroll
            for (int nh = 0; nh < 2; ++nh)
                #pragma unroll
                for (int e = 0; e < 4; ++e) acc[m][nh][e] = 0.0f;

        #pragma unroll
        for (int m = 0; m < 4; ++m) {
            union { uint4 v[4]; uint32_t w[16]; } S;
            {
                const uint32_t* p0 = spkS + (m * 16 + rowq) * SPK_STRIDE + (wid << 3);
                const uint32_t* p1 = spkS + (m * 16 + rowq + 8) * SPK_STRIDE + (wid << 3);
                S.v[0] = *(const uint4*)p0;
                S.v[1] = *(const uint4*)(p0 + 4);
                S.v[2] = *(const uint4*)p1;
                S.v[3] = *(const uint4*)(p1 + 4);
            }
            #pragma unroll
            for (int j = 0; j < 8; ++j) {
                const uint32_t w0 = S.w[j];
                const uint32_t w1 = S.w[8 + j];
                #pragma unroll
                for (int h = 0; h < 2; ++h) {
                    uint2 u0 = lutS[(w0 >> (h * 16 + q4)) & 0xFu];
                    uint2 u1 = lutS[(w1 >> (h * 16 + q4)) & 0xFu];
                    uint32_t a[4] = {u0.x, u1.x, u0.y, u1.y};
                    mma_bf16(acc[m][0], a, bhr[j][h][0], bhr[j][h][1]);
                    mma_bf16(acc[m][1], a, bhr[j][h][2], bhr[j][h][3]);
                    mma_bf16(acc[m][0], a, blr[j][h][0], blr[j][h][1]);
                    mma_bf16(acc[m][1], a, blr[j][h][2], blr[j][h][3]);
                }
            }
        }

        // ---- dump per-warp partials (pair-swizzled: conflict-free) ----
        {
            float* pwrt = redS + wid * 1024;
            #pragma unroll
            for (int m = 0; m < 4; ++m)
                #pragma unroll
                for (int nh = 0; nh < 2; ++nh) {
                    const int mycp = nh * 4 + lc;
                    const int r0 = m * 16 + rowq;
                    const int sw = ((mycp + ((r0 & 2) << 1)) & 7) * 2;
                    *(float2*)(pwrt + r0 * 16 + sw) = make_float2(acc[m][nh][0], acc[m][nh][1]);
                    *(float2*)(pwrt + (r0 + 8) * 16 + sw) = make_float2(acc[m][nh][2], acc[m][nh][3]);
                }
        }
        __syncthreads();

        // ---- reduce 8 partials + LIF epilogue (4 cols per thread) ----
        float2 sa = *(float2*)(redS + rp0);
        float2 sb = *(float2*)(redS + rp1);
        #pragma unroll
        for (int w = 1; w < 8; ++w) {
            float2 pa = *(float2*)(redS + w * 1024 + rp0);
            float2 pb = *(float2*)(redS + w * 1024 + rp1);
            sa.x += pa.x; sa.y += pa.y;
            sb.x += pb.x; sb.y += pb.y;
        }

        float4 mv = *(float4*)(memS + eb * 16 + eq);
        float cur0 = xv.x + sa.x, cur1 = xv.y + sa.y;
        float cur2 = xv.z + sb.x, cur3 = xv.w + sb.y;
        float m0 = (pw & pmask[0]) ? cur0 : fmaf(0.96f, mv.x, cur0);
        float m1 = (pw & pmask[1]) ? cur1 : fmaf(0.96f, mv.y, cur1);
        float m2 = (pw & pmask[2]) ? cur2 : fmaf(0.96f, mv.z, cur2);
        float m3 = (pw & pmask[3]) ? cur3 : fmaf(0.96f, mv.w, cur3);

        unsigned s0 = (m0 >= 0.5f), s1 = (m1 >= 0.5f);
        unsigned s2 = (m2 >= 0.5f), s3 = (m3 >= 0.5f);

        *(float4*)(memS + eb * 16 + eq) = make_float4(m0, m1, m2, m3);

        // pack new spike bits (permuted positions) -> u16 per (batch row, CTA)
        unsigned v = (s0 << npos[0]) | (s1 << npos[1]) | (s2 << npos[2]) | (s3 << npos[3]);
        v |= __shfl_xor_sync(0xFFFFFFFFu, v, 1);
        v |= __shfl_xor_sync(0xFFFFFFFFu, v, 2);
        if ((tid & 3) == 0)
            ((uint16_t*)gdst)[eb * 128 + blockIdx.x] = (uint16_t)v;

        // ---- barrier arrive (spikes visible), overlap out-store with wait ----
        __syncthreads();
        if (tid == 0)
            asm volatile("red.release.gpu.global.add.u32 [%0], 1;" :: "l"(&g_bar) : "memory");

        *(float4*)(out + ((size_t)eb * TT + t) * NN + n0 + eq) =
            make_float4((float)s0, (float)s1, (float)s2, (float)s3);

        if (tid == 0) {
            const unsigned tgt = (unsigned)(CTAS * (t + 1));
            unsigned bv;
            do {
                asm volatile("ld.acquire.gpu.global.u32 %0, [%1];" : "=r"(bv) : "l"(&g_bar) : "memory");
            } while (bv < tgt);
        }
        __syncthreads();
    }
}

// ---- launch ----
extern "C" void kernel_launch(void* const* d_in, const int* in_sizes, int n_in,
                              void* d_out, int out_size) {
    const float* x = (const float*)d_in[0];
    const float* rec = (const float*)d_in[1];
    if (n_in >= 2 && in_sizes[0] == NN * NN) {
        x = (const float*)d_in[1];
        rec = (const float*)d_in[0];
    }
    float* out = (float*)d_out;

    cudaFuncSetAttribute(rsnn_kernel, cudaFuncAttributeMaxDynamicSharedMemorySize, SMEM_TOTAL);

    dim3 cg(NN / 32, NN / 32), cb(32, 32);
    prep_kernel<<<cg, cb>>>(rec);
    rsnn_kernel<<<CTAS, THREADS, SMEM_TOTAL>>>(x, out);
}

// round 16
// speedup vs baseline: 1.3433x; 1.0159x over previous
#include <cuda_runtime.h>
#include <cuda_bf16.h>
#include <cstdint>

#define NN 2048
#define BB 64
#define TT 512
#define CTAS 128
#define THREADS 256
#define PITCHB 4112                 // 2048*2 + 16 bytes, conflict-free ldmatrix rows

// ---- shared memory layout ----
#define OFF_WHI 0
#define OFF_WLO (16 * PITCHB)               // 65792
#define OFF_SPK (32 * PITCHB)               // 131584
#define SPK_STRIDE 68                       // u32 words per spike row (padded)
#define OFF_MEM (OFF_SPK + 64 * SPK_STRIDE * 4)   // 148992
#define OFF_RED (OFF_MEM + 64 * 16 * 4)           // 153088
#define OFF_LUT (OFF_RED + 8 * 64 * 16 * 4)       // 185856
#define SMEM_TOTAL (OFF_LUT + 128)                // 185984

// ---- persistent device state ----
__device__ __align__(16) __nv_bfloat16 g_Whi[NN * NN];    // [n][k] = 0.1*eff^T, hi
__device__ __align__(16) __nv_bfloat16 g_Wlo[NN * NN];    // residual
__device__ __align__(16) uint32_t g_spk0[BB * (NN / 32)]; // bit-permuted packed spikes
__device__ __align__(16) uint32_t g_spk1[BB * (NN / 32)];
__device__ uint32_t g_bar;

// Spike bit permutation: within each 16-bit half (h = k>=16), local c = k&15 sits at
//   np(c) = ((c&7)>>1)*4 + (c&1) + 2*((c>>3)&1)
// so nibble q of a half = bits {k=2q, 2q+1, 2q+8, 2q+9}: one lane's A-pair bits.

// ---- helpers ----
__device__ __forceinline__ uint32_t smem_u32(const void* p) {
    uint32_t a;
    asm("{ .reg .u64 t; cvta.to.shared.u64 t, %1; cvt.u32.u64 %0, t; }" : "=r"(a) : "l"(p));
    return a;
}

__device__ __forceinline__ void ldsm4(uint32_t* r, uint32_t addr) {
    asm volatile("ldmatrix.sync.aligned.m8n8.x4.shared.b16 {%0,%1,%2,%3}, [%4];"
                 : "=r"(r[0]), "=r"(r[1]), "=r"(r[2]), "=r"(r[3]) : "r"(addr));
}

__device__ __forceinline__ void mma_bf16(float* c, const uint32_t* a, uint32_t b0, uint32_t b1) {
    asm volatile(
        "mma.sync.aligned.m16n8k16.row.col.f32.bf16.bf16.f32 "
        "{%0,%1,%2,%3},{%4,%5,%6,%7},{%8,%9},{%0,%1,%2,%3};"
        : "+f"(c[0]), "+f"(c[1]), "+f"(c[2]), "+f"(c[3])
        : "r"(a[0]), "r"(a[1]), "r"(a[2]), "r"(a[3]), "r"(b0), "r"(b1));
}

// ---- prep: transpose + zero diag + 0.1 scale + bf16 hi/lo split, plus state init ----
__global__ void prep_kernel(const float* __restrict__ rec) {
    __shared__ float tile[32][33];
    int k = blockIdx.y * 32 + threadIdx.y;
    int n = blockIdx.x * 32 + threadIdx.x;
    tile[threadIdx.y][threadIdx.x] = rec[k * NN + n];

    int fb = blockIdx.y * gridDim.x + blockIdx.x;
    int ft = threadIdx.y * 32 + threadIdx.x;
    if (fb < 4)      g_spk0[fb * 1024 + ft] = 0u;
    else if (fb < 8) g_spk1[(fb - 4) * 1024 + ft] = 0u;
    else if (fb == 8 && ft == 0) g_bar = 0u;

    __syncthreads();
    int nn = blockIdx.x * 32 + threadIdx.y;
    int kk = blockIdx.y * 32 + threadIdx.x;
    float w = tile[threadIdx.x][threadIdx.y];      // rec[kk][nn]
    float v = (nn == kk) ? 0.0f : 0.1f * w;
    __nv_bfloat16 hi = __float2bfloat16(v);
    float resid = v - __bfloat162float(hi);
    g_Whi[nn * NN + kk] = hi;
    g_Wlo[nn * NN + kk] = __float2bfloat16(resid);
}

// ---- persistent RSNN kernel: 128 CTAs, one per 16-neuron slice, 8 warps ----
__global__ void __launch_bounds__(THREADS)
rsnn_kernel(const float* __restrict__ x, float* __restrict__ out) {
    extern __shared__ char smem[];
    const uint32_t sbase = smem_u32(smem);

    const int tid = threadIdx.x;
    const int wid = tid >> 5;           // warp = k-eighth (8 u32 spike words)
    const int lane = tid & 31;
    const int n0 = blockIdx.x * 16;

    // ---- load weight slice into SMEM once (hi + lo, pitched) ----
    for (int i = tid; i < 16 * 256; i += THREADS) {
        int row = i >> 8, c = i & 255;
        *(uint4*)(smem + OFF_WHI + row * PITCHB + c * 16) =
            *(const uint4*)(g_Whi + (size_t)(n0 + row) * NN + c * 8);
        *(uint4*)(smem + OFF_WLO + row * PITCHB + c * 16) =
            *(const uint4*)(g_Wlo + (size_t)(n0 + row) * NN + c * 8);
    }
    for (int i = tid; i < 64 * 16; i += THREADS)
        ((float*)(smem + OFF_MEM))[i] = 0.0f;
    // nibble -> (a_low, a_high) bf16x2 LUT; conflict-free bank sweep
    if (tid < 16) {
        uint2 e;
        e.x = ((tid & 1) ? 0x00003F80u : 0u) | ((tid & 2) ? 0x3F800000u : 0u);
        e.y = ((tid & 4) ? 0x00003F80u : 0u) | ((tid & 8) ? 0x3F800000u : 0u);
        ((uint2*)(smem + OFF_LUT))[tid] = e;
    }
    __syncthreads();

    // per-thread constants (GEMM)
    const int rowq = lane >> 2;           // 0..7
    const int q4 = (lane & 3) * 4;        // nibble shift within a 16-bit half
    const int lc = lane & 3;
    uint32_t ldsm_off;
    {
        int grp = lane >> 3;                          // 8x8 matrix select
        int row = ((grp >> 1) << 3) + (lane & 7);     // local neuron row 0..15
        int koff = (grp & 1) * 8;
        ldsm_off = row * PITCHB + koff * 2;
    }

    // ---- hoist ALL B fragments (hi + lo) into registers: loaded ONCE ----
    uint32_t bhr[8][2][4], blr[8][2][4];
    #pragma unroll
    for (int j = 0; j < 8; ++j) {
        const int widx = (wid << 3) + j;
        #pragma unroll
        for (int h = 0; h < 2; ++h) {
            const int kt = widx * 2 + h;
            ldsm4(bhr[j][h], sbase + OFF_WHI + ldsm_off + kt * 32);
            ldsm4(blr[j][h], sbase + OFF_WLO + ldsm_off + kt * 32);
        }
    }

    // per-thread constants (epilogue: 256 threads, 4 cols each)
    const int eb = tid >> 2;              // batch row 0..63
    const int eq = (tid & 3) * 4;         // col base 0..12
    const int wsel = n0 >> 5;
    const int hsh = ((n0 >> 4) & 1) * 16;

    int npos[4];
    uint32_t pmask[4];
    #pragma unroll
    for (int i = 0; i < 4; ++i) {
        int c = eq + i;
        npos[i] = ((c & 7) >> 1) * 4 + (c & 1) + 2 * ((c >> 3) & 1);
        pmask[i] = 1u << (hsh + npos[i]);
    }
    // swizzled reduce pair offsets (pair swizzle: p = (cp + ((eb&2)<<1)) & 7)
    const int cp0 = (tid & 3) * 2;
    const int rp0 = eb * 16 + ((cp0 + ((eb & 2) << 1)) & 7) * 2;
    const int rp1 = eb * 16 + (((cp0 + 1) + ((eb & 2) << 1)) & 7) * 2;

    uint32_t* const spkS = (uint32_t*)(smem + OFF_SPK);
    float* const memS = (float*)(smem + OFF_MEM);
    float* const redS = (float*)(smem + OFF_RED);
    const uint2* const lutS = (const uint2*)(smem + OFF_LUT);

    // x prefetch carried across iterations (loaded for t=0 here)
    float4 xv = __ldg((const float4*)(x + (size_t)eb * TT * NN + n0 + eq));

    for (int t = 0; t < TT; ++t) {
        const uint32_t* gsrc = (t & 1) ? g_spk1 : g_spk0;
        uint32_t* gdst = (t & 1) ? g_spk0 : g_spk1;

        // ---- stage packed spikes [64 x 64 u32] -> padded SMEM rows ----
        {
            const uint4* src = (const uint4*)gsrc;
            #pragma unroll
            for (int i = tid; i < 1024; i += THREADS) {
                int row = i >> 4, c4 = i & 15;
                uint4 v = __ldcg(src + i);
                *(uint4*)(smem + OFF_SPK + (row * SPK_STRIDE + c4 * 4) * 4) = v;
            }
        }
        __syncthreads();

        // prev-spike word (reset mask) — hoisted off the post-dump critical path
        const uint32_t pw = spkS[eb * SPK_STRIDE + wsel];

        // ---- GEMM: warp owns a k-eighth, B resident in registers ----
        // m-outer / j-inner, software-pipelined uint4 spike-word loads.
        float acc[4][2][4];
        #pragma unroll
        for (int m = 0; m < 4; ++m)
            #pragma unroll
            for (int nh = 0; nh < 2; ++nh)
                #pragma unroll
                for (int e = 0; e < 4; ++e) acc[m][nh][e] = 0.0f;

        union Sreg { uint4 v[4]; uint32_t w[16]; };
        Sreg S, Snext;
        {
            const uint32_t* p0 = spkS + rowq * SPK_STRIDE + (wid << 3);
            const uint32_t* p1 = spkS + (rowq + 8) * SPK_STRIDE + (wid << 3);
            S.v[0] = *(const uint4*)p0;
            S.v[1] = *(const uint4*)(p0 + 4);
            S.v[2] = *(const uint4*)p1;
            S.v[3] = *(const uint4*)(p1 + 4);
        }
        #pragma unroll
        for (int m = 0; m < 4; ++m) {
            if (m < 3) {   // prefetch next m-tile's spike words under this m's MMAs
                const uint32_t* p0 = spkS + ((m + 1) * 16 + rowq) * SPK_STRIDE + (wid << 3);
                const uint32_t* p1 = spkS + ((m + 1) * 16 + rowq + 8) * SPK_STRIDE + (wid << 3);
                Snext.v[0] = *(const uint4*)p0;
                Snext.v[1] = *(const uint4*)(p0 + 4);
                Snext.v[2] = *(const uint4*)p1;
                Snext.v[3] = *(const uint4*)(p1 + 4);
            }
            #pragma unroll
            for (int j = 0; j < 8; ++j) {
                const uint32_t w0 = S.w[j];
                const uint32_t w1 = S.w[8 + j];
                #pragma unroll
                for (int h = 0; h < 2; ++h) {
                    uint2 u0 = lutS[(w0 >> (h * 16 + q4)) & 0xFu];
                    uint2 u1 = lutS[(w1 >> (h * 16 + q4)) & 0xFu];
                    uint32_t a[4] = {u0.x, u1.x, u0.y, u1.y};
                    mma_bf16(acc[m][0], a, bhr[j][h][0], bhr[j][h][1]);
                    mma_bf16(acc[m][1], a, bhr[j][h][2], bhr[j][h][3]);
                    mma_bf16(acc[m][0], a, blr[j][h][0], blr[j][h][1]);
                    mma_bf16(acc[m][1], a, blr[j][h][2], blr[j][h][3]);
                }
            }
            if (m < 3) S = Snext;
        }

        // ---- dump per-warp partials (pair-swizzled: conflict-free) ----
        {
            float* pwrt = redS + wid * 1024;
            #pragma unroll
            for (int m = 0; m < 4; ++m)
                #pragma unroll
                for (int nh = 0; nh < 2; ++nh) {
                    const int mycp = nh * 4 + lc;
                    const int r0 = m * 16 + rowq;
                    const int sw = ((mycp + ((r0 & 2) << 1)) & 7) * 2;
                    *(float2*)(pwrt + r0 * 16 + sw) = make_float2(acc[m][nh][0], acc[m][nh][1]);
                    *(float2*)(pwrt + (r0 + 8) * 16 + sw) = make_float2(acc[m][nh][2], acc[m][nh][3]);
                }
        }
        __syncthreads();

        // ---- reduce 8 partials + LIF epilogue (4 cols per thread) ----
        float2 sa = *(float2*)(redS + rp0);
        float2 sb = *(float2*)(redS + rp1);
        #pragma unroll
        for (int w = 1; w < 8; ++w) {
            float2 pa = *(float2*)(redS + w * 1024 + rp0);
            float2 pb = *(float2*)(redS + w * 1024 + rp1);
            sa.x += pa.x; sa.y += pa.y;
            sb.x += pb.x; sb.y += pb.y;
        }

        float4 mv = *(float4*)(memS + eb * 16 + eq);
        float cur0 = xv.x + sa.x, cur1 = xv.y + sa.y;
        float cur2 = xv.z + sb.x, cur3 = xv.w + sb.y;
        float m0 = (pw & pmask[0]) ? cur0 : fmaf(0.96f, mv.x, cur0);
        float m1 = (pw & pmask[1]) ? cur1 : fmaf(0.96f, mv.y, cur1);
        float m2 = (pw & pmask[2]) ? cur2 : fmaf(0.96f, mv.z, cur2);
        float m3 = (pw & pmask[3]) ? cur3 : fmaf(0.96f, mv.w, cur3);

        unsigned s0 = (m0 >= 0.5f), s1 = (m1 >= 0.5f);
        unsigned s2 = (m2 >= 0.5f), s3 = (m3 >= 0.5f);

        *(float4*)(memS + eb * 16 + eq) = make_float4(m0, m1, m2, m3);

        // pack new spike bits (permuted positions) -> u16 per (batch row, CTA)
        unsigned v = (s0 << npos[0]) | (s1 << npos[1]) | (s2 << npos[2]) | (s3 << npos[3]);
        v |= __shfl_xor_sync(0xFFFFFFFFu, v, 1);
        v |= __shfl_xor_sync(0xFFFFFFFFu, v, 2);
        if ((tid & 3) == 0)
            ((uint16_t*)gdst)[eb * 128 + blockIdx.x] = (uint16_t)v;

        // ---- barrier arrive (spikes visible), overlap stores + x-prefetch with wait ----
        __syncthreads();
        if (tid == 0)
            asm volatile("red.release.gpu.global.add.u32 [%0], 1;" :: "l"(&g_bar) : "memory");

        *(float4*)(out + ((size_t)eb * TT + t) * NN + n0 + eq) =
            make_float4((float)s0, (float)s1, (float)s2, (float)s3);

        // prefetch x for step t+1 (hidden under the poll + next stage)
        if (t + 1 < TT)
            xv = __ldg((const float4*)(x + ((size_t)eb * TT + t + 1) * NN + n0 + eq));

        if (tid == 0) {
            const unsigned tgt = (unsigned)(CTAS * (t + 1));
            unsigned bv;
            do {
                asm volatile("ld.acquire.gpu.global.u32 %0, [%1];" : "=r"(bv) : "l"(&g_bar) : "memory");
            } while (bv < tgt);
        }
        __syncthreads();
    }
}

// ---- launch ----
extern "C" void kernel_launch(void* const* d_in, const int* in_sizes, int n_in,
                              void* d_out, int out_size) {
    const float* x = (const float*)d_in[0];
    const float* rec = (const float*)d_in[1];
    if (n_in >= 2 && in_sizes[0] == NN * NN) {
        x = (const float*)d_in[1];
        rec = (const float*)d_in[0];
    }
    float* out = (float*)d_out;

    cudaFuncSetAttribute(rsnn_kernel, cudaFuncAttributeMaxDynamicSharedMemorySize, SMEM_TOTAL);

    dim3 cg(NN / 32, NN / 32), cb(32, 32);
    prep_kernel<<<cg, cb>>>(rec);
    rsnn_kernel<<<CTAS, THREADS, SMEM_TOTAL>>>(x, out);
}